// round 16
// baseline (speedup 1.0000x reference)
#include <cuda_runtime.h>
#include <cuda_bf16.h>
#include <cuda_fp8.h>
#include <cstdint>

#define LL 512
#define DD 128
#define NCTA 128

// ---------------- scratch globals ----------------
__device__ float g_keep[LL];
__device__ float g_seq[LL * DD];
__device__ float g_Q[LL * DD];
__device__ float g_qp[LL * DD];
__device__ float g_kp[LL * DD];
__device__ float g_vp[LL * DD];
__device__ float g_twlog[2 * LL * LL];
__device__ __align__(16) uint8_t g_Bimg8[2 * 128 * 128];  // e4m3(64*Wt[s][k][n]) as [s][n][k]

__device__ unsigned g_bar_count;
__device__ volatile unsigned g_bar_gen;

__device__ __forceinline__ void grid_barrier() {
    __syncthreads();
    if (threadIdx.x == 0) {
        __threadfence();
        unsigned gen = g_bar_gen;
        if (atomicAdd(&g_bar_count, 1u) == NCTA - 1) {
            atomicExch(&g_bar_count, 0u);
            __threadfence();
            g_bar_gen = gen + 1u;
        } else {
            while (g_bar_gen == gen) __nanosleep(32);
        }
        __threadfence();
    }
    __syncthreads();
}

__device__ __forceinline__ uint32_t smem_to_u32(const void* p) {
    uint32_t a;
    asm("{ .reg .u64 t; cvta.to.shared.u64 t, %1; cvt.u32.u64 %0, t; }" : "=r"(a) : "l"(p));
    return a;
}
__device__ __forceinline__ void cp_async16(uint32_t dst, const void* src) {
    asm volatile("cp.async.cg.shared.global [%0], [%1], 16;" :: "r"(dst), "l"(src));
}
#define CP_COMMIT() asm volatile("cp.async.commit_group;")
#define CP_WAIT(n)  asm volatile("cp.async.wait_group %0;" :: "n"(n))

// fp8 e4m3 MMA: D[16x8] += A[16x32] * B[32x8], fp32 accum
__device__ __forceinline__ void mma_fp8(float* c, const uint32_t* a, uint32_t b0, uint32_t b1) {
    asm volatile(
        "mma.sync.aligned.m16n8k32.row.col.f32.e4m3.e4m3.f32 "
        "{%0,%1,%2,%3}, {%4,%5,%6,%7}, {%8,%9}, {%0,%1,%2,%3};"
        : "+f"(c[0]), "+f"(c[1]), "+f"(c[2]), "+f"(c[3])
        : "r"(a[0]), "r"(a[1]), "r"(a[2]), "r"(a[3]), "r"(b0), "r"(b1));
}

// pack 4 floats -> 4 e4m3 bytes (byte i = element i)
__device__ __forceinline__ uint32_t pack_e4m3x4(float4 a) {
    uint16_t lo, hi;
    asm("cvt.rn.satfinite.e4m3x2.f32 %0, %1, %2;" : "=h"(lo) : "f"(a.y), "f"(a.x));
    asm("cvt.rn.satfinite.e4m3x2.f32 %0, %1, %2;" : "=h"(hi) : "f"(a.w), "f"(a.z));
    return (uint32_t)lo | ((uint32_t)hi << 16);
}

// ---------------- B images: g_Bimg8[s][n][k] = e4m3(64 * Wt[s][k][n]) --------
__global__ void bimg_kernel(const float* __restrict__ Wt) {
    int id = blockIdx.x * 256 + threadIdx.x;  // 32768
    int s = id >> 14, e = id & 16383;
    int n = e >> 7, k = e & 127;
    float v = Wt[s * 16384 + k * 128 + n] * 64.0f;
    g_Bimg8[id] = (uint8_t)__nv_cvt_float_to_fp8(v, __NV_SATFINITE, __NV_E4M3);
}

// ---------------- time-bias kernel: fp8 MMA + cp.async streamed A tile -------
// smem: A fp8 128x144, B 2x128x144, scalars, fp32 staging 2x16KB
#define TW_SA   0
#define TW_SB   18432
#define TW_SSC  (TW_SB + 36864)          // 55296
#define TW_STG  (TW_SSC + 2064)          // 57360
#define TW_SMEM (TW_STG + 32768)         // 90128

__global__ void __launch_bounds__(256, 2)
twbias_kernel(const float* __restrict__ T, const float* __restrict__ bt,
              const float* __restrict__ Wtp, const float* __restrict__ btp) {
    extern __shared__ char smem[];
    int tid = threadIdx.x;
    float* sc = (float*)(smem + TW_SSC);
    uint32_t stg_u32 = smem_to_u32(smem + TW_STG);

    // kick off chunk 0 of the A stream immediately (32 rows = 16KB fp32)
    const float* Tbase = T + (size_t)blockIdx.x * 128 * 128;
#pragma unroll
    for (int j = 0; j < 4; j++) {
        int t = tid + 256 * j;                    // 1024 16B-chunks per 32 rows
        cp_async16(stg_u32 + t * 16, (const char*)Tbase + t * 16);
    }
    CP_COMMIT();

    {   // stage B images: 256 rows x 128B -> padded 144B rows
        const uint4* src = (const uint4*)g_Bimg8;   // 2048 uint4
        for (int i = tid; i < 2048; i += 256) {
            int r = i >> 3, w8 = i & 7;             // row r in [0,256), 16B chunk w8
            int s = r >> 7, n = r & 127;
            *(uint4*)(smem + TW_SB + s * 18432 + n * 144 + w8 * 16) = src[i];
        }
    }
    if (tid < 128) {
        sc[tid]       = bt[tid];
        sc[128 + tid] = bt[128 + tid];
        sc[256 + tid] = Wtp[tid];
        sc[384 + tid] = Wtp[128 + tid];
    }
    if (tid == 0) { sc[512] = btp[0]; sc[513] = btp[1]; }

    // pipelined A stream: 4 chunks of 32 rows, double-buffered staging
#pragma unroll 1
    for (int c = 0; c < 4; c++) {
        if (c < 3) {   // issue chunk c+1
            uint32_t dst = stg_u32 + ((c + 1) & 1) * 16384;
            const char* src = (const char*)(Tbase + (c + 1) * 32 * 128);
#pragma unroll
            for (int j = 0; j < 4; j++) {
                int t = tid + 256 * j;
                cp_async16(dst + t * 16, src + t * 16);
            }
            CP_COMMIT();
            CP_WAIT(1);   // chunk c ready
        } else {
            CP_WAIT(0);
        }
        __syncthreads();
        // convert chunk c: 1024 float4 -> fp8 rows [c*32, c*32+32)
        const float4* stg = (const float4*)(smem + TW_STG + (c & 1) * 16384);
#pragma unroll
        for (int j = 0; j < 4; j++) {
            int t = tid + 256 * j;
            int r = t >> 5, kc = (t & 31) << 2;
            *(uint32_t*)(smem + TW_SA + (c * 32 + r) * 144 + kc) = pack_e4m3x4(stg[t]);
        }
        __syncthreads();
    }

    int lane = tid & 31, w = tid >> 5;
    int s = w >> 2, mrow0 = (w & 3) * 32;
    int gid = lane >> 2, tig = lane & 3;

    // A fragments: 2 mtiles x 4 ktiles x 4 regs (PTX m16n8k32 f8 layout)
    uint32_t a8[2][4][4];
#pragma unroll
    for (int mt = 0; mt < 2; mt++)
#pragma unroll
        for (int kt = 0; kt < 4; kt++) {
            const char* rp0 = smem + TW_SA + (mrow0 + mt * 16 + gid) * 144;
            const char* rp1 = rp0 + 8 * 144;
            int k0 = kt * 32 + tig * 4;
            a8[mt][kt][0] = *(const uint32_t*)(rp0 + k0);
            a8[mt][kt][1] = *(const uint32_t*)(rp1 + k0);
            a8[mt][kt][2] = *(const uint32_t*)(rp0 + k0 + 16);
            a8[mt][kt][3] = *(const uint32_t*)(rp1 + k0 + 16);
        }

    const char* b_base = smem + TW_SB + s * 18432;
    const float IS = 0.015625f;   // 1/64: undo the Wt*64 quantization scale

    float accR[2][2] = {{0.f, 0.f}, {0.f, 0.f}};
#pragma unroll
    for (int nt = 0; nt < 16; nt++) {
        float c[2][4];
#pragma unroll
        for (int mt = 0; mt < 2; mt++)
#pragma unroll
            for (int t = 0; t < 4; t++) c[mt][t] = 0.f;
        const char* brow = b_base + (nt * 8 + gid) * 144;
#pragma unroll
        for (int kt = 0; kt < 4; kt++) {
            int k0 = kt * 32 + tig * 4;
            uint32_t b0 = *(const uint32_t*)(brow + k0);
            uint32_t b1 = *(const uint32_t*)(brow + k0 + 16);
            mma_fp8(c[0], a8[0][kt], b0, b1);
            mma_fp8(c[1], a8[1][kt], b0, b1);
        }
        int n0 = nt * 8 + 2 * tig;
        float bt0 = sc[s * 128 + n0],       bt1 = sc[s * 128 + n0 + 1];
        float wp0 = sc[256 + s * 128 + n0], wp1 = sc[256 + s * 128 + n0 + 1];
        accR[0][0] += fmaxf(fmaf(c[0][0], IS, bt0), 0.f) * wp0 + fmaxf(fmaf(c[0][1], IS, bt1), 0.f) * wp1;
        accR[0][1] += fmaxf(fmaf(c[0][2], IS, bt0), 0.f) * wp0 + fmaxf(fmaf(c[0][3], IS, bt1), 0.f) * wp1;
        accR[1][0] += fmaxf(fmaf(c[1][0], IS, bt0), 0.f) * wp0 + fmaxf(fmaf(c[1][1], IS, bt1), 0.f) * wp1;
        accR[1][1] += fmaxf(fmaf(c[1][2], IS, bt0), 0.f) * wp0 + fmaxf(fmaf(c[1][3], IS, bt1), 0.f) * wp1;
    }
    // reduce over quad
#pragma unroll
    for (int o = 1; o <= 2; o <<= 1) {
        accR[0][0] += __shfl_xor_sync(0xffffffffu, accR[0][0], o);
        accR[0][1] += __shfl_xor_sync(0xffffffffu, accR[0][1], o);
        accR[1][0] += __shfl_xor_sync(0xffffffffu, accR[1][0], o);
        accR[1][1] += __shfl_xor_sync(0xffffffffu, accR[1][1], o);
    }
    if ((lane & 3) == 0) {
        int g = lane >> 2;
        float bp = sc[512 + s];
#pragma unroll
        for (int mt = 0; mt < 2; mt++)
#pragma unroll
            for (int hh = 0; hh < 2; hh++) {
                int row = mrow0 + mt * 16 + hh * 8 + g;
                size_t p = (size_t)blockIdx.x * 128 + (size_t)row;
                float tp = accR[mt][hh] + bp;
                float lg = (tp >= 0.f) ? -log1pf(expf(-tp)) : tp - log1pf(expf(tp));
                g_twlog[(size_t)s * (LL * LL) + p] = lg;
            }
    }
}

// ---- warp-cooperative row LN stats: warps 0-3 reduce rows 0-3 of rowbuf[4][128]
__device__ __forceinline__ void row_stats(const float* rowbuf, float* stats,
                                          int w, int lane) {
    if (w < 4) {
        float s = 0.f, s2 = 0.f;
#pragma unroll
        for (int j = 0; j < 4; j++) {
            float v = rowbuf[w * 128 + lane + 32 * j];
            s += v; s2 += v * v;
        }
#pragma unroll
        for (int o = 16; o; o >>= 1) {
            s  += __shfl_xor_sync(0xffffffffu, s, o);
            s2 += __shfl_xor_sync(0xffffffffu, s2, o);
        }
        if (lane == 0) {
            float m = s * (1.0f / DD);
            float var = s2 * (1.0f / DD) - m * m;
            stats[w * 2]     = m;
            stats[w * 2 + 1] = rsqrtf(var + 1e-8f);
        }
    }
    __syncthreads();
}

// ---------------- persistent fused tail (R12 form): 128 CTAs x 512 thr ------
#define TAIL_SMEM (2 * 512 * 33 * 4)    // 135168 B

__global__ void __launch_bounds__(512)
tail_kernel(const int* __restrict__ logs, const float* __restrict__ seqs,
            const float* __restrict__ Wq, const float* __restrict__ bq,
            const float* __restrict__ Wk, const float* __restrict__ bk,
            const float* __restrict__ Wv, const float* __restrict__ bv,
            const float* __restrict__ ln1g, const float* __restrict__ ln1b,
            const float* __restrict__ ln2g, const float* __restrict__ ln2b,
            const float* __restrict__ W1, const float* __restrict__ b1,
            const float* __restrict__ W2, const float* __restrict__ b2,
            const float* __restrict__ lnfg, const float* __restrict__ lnfb,
            float* __restrict__ out) {
    extern __shared__ float fsm[];
    float* rows_raw = fsm;
    float* rows_ln  = fsm + 512;
    float* hbuf     = fsm + 1024;
    float* stats    = fsm + 1536;
    float* Ws       = fsm + 2048;

    int cta = blockIdx.x, tid = threadIdx.x;
    int lane = tid & 31, w = tid >> 5;
    int trow = tid >> 7, tcol = tid & 127;
    int grow = cta * 4 + trow;
    const float NEGV = -4294967295.0f;
    const float SCALE = 0.17677669529663689f;  // 1/sqrt(32)

    for (int i = 0; i < 2; i++) {
        const int wo = i * 16384, bo = i * 128;

        // ======== phase A: (prep +) ln1 + Q/K/V for own 4 rows ========
        if (i == 0) {
            float kmask = (logs[grow] == 0) ? 0.f : 1.f;
            rows_raw[tid] = seqs[grow * 128 + tcol] * kmask;
            if (tcol == 0) g_keep[grow] = kmask;
        } else {
            rows_raw[tid] = g_seq[grow * 128 + tcol];
        }
        __syncthreads();
        row_stats(rows_raw, stats, w, lane);
        {
            float m = stats[trow * 2], rinv = stats[trow * 2 + 1];
            float lv = (rows_raw[tid] - m) * rinv * ln1g[bo + tcol] + ln1b[bo + tcol];
            rows_ln[tid] = lv;
            g_Q[grow * 128 + tcol] = lv;
        }
        __syncthreads();
#pragma unroll 1
        for (int z = 0; z < 3; z++) {
            const float* W    = (z == 0) ? Wq + wo : (z == 1) ? Wk + wo : Wv + wo;
            const float* bias = (z == 0) ? bq + bo : (z == 1) ? bk + bo : bv + bo;
            float* C          = (z == 0) ? g_qp : (z == 1) ? g_kp : g_vp;
            const float4* Wsrc = (const float4*)W;
            float4* Wdst = (float4*)Ws;
#pragma unroll
            for (int j = 0; j < 8; j++) Wdst[tid + 512 * j] = Wsrc[tid + 512 * j];
            __syncthreads();
            const float* src = (z == 0) ? rows_ln : rows_raw;
            float a0 = 0.f, a1 = 0.f, a2 = 0.f, a3 = 0.f;
#pragma unroll
            for (int k = 0; k < 128; k += 4) {
                a0 += src[trow * 128 + k]     * Ws[(k) * 128 + tcol];
                a1 += src[trow * 128 + k + 1] * Ws[(k + 1) * 128 + tcol];
                a2 += src[trow * 128 + k + 2] * Ws[(k + 2) * 128 + tcol];
                a3 += src[trow * 128 + k + 3] * Ws[(k + 3) * 128 + tcol];
            }
            C[grow * 128 + tcol] = (a0 + a1) + (a2 + a3) + bias[tcol];
            __syncthreads();
        }
        grid_barrier();

        // ======== phase B: attention, CTA=(h, q-chunk of 16), warp-per-q ====
        {
            float* ks = fsm;
            float* vs = fsm + 512 * 33;
            int h = cta >> 5, q0 = (cta & 31) * 16;
            for (int t = tid; t < 512 * 32; t += 512) {
                int kk = t >> 5, d = t & 31;
                ks[kk * 33 + d] = g_kp[kk * 128 + h * 32 + d];
                vs[kk * 33 + d] = g_vp[kk * 128 + h * 32 + d];
            }
            __syncthreads();
            float* wout = out + 65536 + (size_t)i * 1048576;
            int q = q0 + w;
            float qreg[32];
            const float4* q4 = (const float4*)(g_qp + q * 128 + h * 32);
#pragma unroll
            for (int j = 0; j < 8; j++) {
                float4 t4 = q4[j];
                qreg[j * 4]     = t4.x; qreg[j * 4 + 1] = t4.y;
                qreg[j * 4 + 2] = t4.z; qreg[j * 4 + 3] = t4.w;
            }
            bool padq = (g_keep[q] == 0.0f);
            const float* tw = g_twlog + (size_t)i * (LL * LL) + (size_t)q * 512;
            float sv[16];
            float mx = -3.4e38f;
#pragma unroll
            for (int blk = 0; blk < 16; blk++) {
                int kk = blk * 32 + lane;
                float d0 = 0.f, d1 = 0.f;
#pragma unroll
                for (int d = 0; d < 32; d += 2) {
                    d0 += qreg[d]     * ks[kk * 33 + d];
                    d1 += qreg[d + 1] * ks[kk * 33 + d + 1];
                }
                float sva = (padq || kk > q) ? NEGV : ((d0 + d1) + tw[kk]) * SCALE;
                sv[blk] = sva;
                mx = fmaxf(mx, sva);
            }
#pragma unroll
            for (int o = 16; o; o >>= 1) mx = fmaxf(mx, __shfl_xor_sync(0xffffffffu, mx, o));
            float sum = 0.f;
#pragma unroll
            for (int blk = 0; blk < 16; blk++) {
                float e = expf(sv[blk] - mx);
                sv[blk] = e;
                sum += e;
            }
#pragma unroll
            for (int o = 16; o; o >>= 1) sum += __shfl_xor_sync(0xffffffffu, sum, o);
            float inv = 1.0f / sum;
#pragma unroll
            for (int blk = 0; blk < 16; blk++) {
                float wv = sv[blk] * inv;
                sv[blk] = wv;
                wout[(size_t)h * 262144 + (size_t)q * 512 + blk * 32 + lane] = wv;
            }
            float ac0 = 0.f, ac1 = 0.f, ac2 = 0.f, ac3 = 0.f;
#pragma unroll
            for (int blk = 0; blk < 16; blk++) {
#pragma unroll
                for (int src = 0; src < 32; src += 4) {
                    ac0 += __shfl_sync(0xffffffffu, sv[blk], src)     * vs[(blk * 32 + src) * 33 + lane];
                    ac1 += __shfl_sync(0xffffffffu, sv[blk], src + 1) * vs[(blk * 32 + src + 1) * 33 + lane];
                    ac2 += __shfl_sync(0xffffffffu, sv[blk], src + 2) * vs[(blk * 32 + src + 2) * 33 + lane];
                    ac3 += __shfl_sync(0xffffffffu, sv[blk], src + 3) * vs[(blk * 32 + src + 3) * 33 + lane];
                }
            }
            float acc = (ac0 + ac1) + (ac2 + ac3);
            g_seq[q * 128 + h * 32 + lane] = g_Q[q * 128 + h * 32 + lane] + acc;
            __syncthreads();
        }
        grid_barrier();

        // ======== phase C: ln2 + FFN1 (own rows, h kept in smem) ========
        rows_raw[tid] = g_seq[grow * 128 + tcol];
        __syncthreads();
        row_stats(rows_raw, stats, w, lane);
        {
            float m = stats[trow * 2], rinv = stats[trow * 2 + 1];
            rows_ln[tid] = (rows_raw[tid] - m) * rinv * ln2g[bo + tcol] + ln2b[bo + tcol];
        }
        __syncthreads();
        {
            const float4* Wsrc = (const float4*)(W1 + wo);
            float4* Wdst = (float4*)Ws;
#pragma unroll
            for (int j = 0; j < 8; j++) Wdst[tid + 512 * j] = Wsrc[tid + 512 * j];
            __syncthreads();
            float a0 = 0.f, a1 = 0.f, a2 = 0.f, a3 = 0.f;
#pragma unroll
            for (int k = 0; k < 128; k += 4) {
                a0 += rows_ln[trow * 128 + k]     * Ws[(k) * 128 + tcol];
                a1 += rows_ln[trow * 128 + k + 1] * Ws[(k + 1) * 128 + tcol];
                a2 += rows_ln[trow * 128 + k + 2] * Ws[(k + 2) * 128 + tcol];
                a3 += rows_ln[trow * 128 + k + 3] * Ws[(k + 3) * 128 + tcol];
            }
            hbuf[tid] = fmaxf((a0 + a1) + (a2 + a3) + b1[bo + tcol], 0.f);
            __syncthreads();
        }
        // ======== phase D: FFN2 (local) ========
        {
            const float4* Wsrc = (const float4*)(W2 + wo);
            float4* Wdst = (float4*)Ws;
#pragma unroll
            for (int j = 0; j < 8; j++) Wdst[tid + 512 * j] = Wsrc[tid + 512 * j];
            __syncthreads();
            float a0 = 0.f, a1 = 0.f, a2 = 0.f, a3 = 0.f;
#pragma unroll
            for (int k = 0; k < 128; k += 4) {
                a0 += hbuf[trow * 128 + k]     * Ws[(k) * 128 + tcol];
                a1 += hbuf[trow * 128 + k + 1] * Ws[(k + 1) * 128 + tcol];
                a2 += hbuf[trow * 128 + k + 2] * Ws[(k + 2) * 128 + tcol];
                a3 += hbuf[trow * 128 + k + 3] * Ws[(k + 3) * 128 + tcol];
            }
            float y = (a0 + a1) + (a2 + a3) + b2[bo + tcol];
            g_seq[grow * 128 + tcol] = (rows_ln[tid] + y) * g_keep[grow];
            __syncthreads();
        }
        // no grid barrier: next phase A / lnf read only own rows
    }

    // ======== final LayerNorm (own rows) ========
    rows_raw[tid] = g_seq[grow * 128 + tcol];
    __syncthreads();
    row_stats(rows_raw, stats, w, lane);
    {
        float m = stats[trow * 2], rinv = stats[trow * 2 + 1];
        out[grow * 128 + tcol] =
            (rows_raw[tid] - m) * rinv * lnfg[tcol] + lnfb[tcol];
    }
}

// ---------------- launch ----------------
extern "C" void kernel_launch(void* const* d_in, const int* in_sizes, int n_in,
                              void* d_out, int out_size) {
    const int*   logs = (const int*)d_in[0];
    const float* seqs = (const float*)d_in[1];
    const float* tmk  = (const float*)d_in[2];
    const float* Wq   = (const float*)d_in[3];
    const float* bq   = (const float*)d_in[4];
    const float* Wk   = (const float*)d_in[5];
    const float* bk   = (const float*)d_in[6];
    const float* Wv   = (const float*)d_in[7];
    const float* bv   = (const float*)d_in[8];
    const float* Wt   = (const float*)d_in[9];
    const float* bt   = (const float*)d_in[10];
    const float* Wtp  = (const float*)d_in[11];
    const float* btp  = (const float*)d_in[12];
    const float* ln1g = (const float*)d_in[13];
    const float* ln1b = (const float*)d_in[14];
    const float* ln2g = (const float*)d_in[15];
    const float* ln2b = (const float*)d_in[16];
    const float* W1   = (const float*)d_in[17];
    const float* b1   = (const float*)d_in[18];
    const float* W2   = (const float*)d_in[19];
    const float* b2   = (const float*)d_in[20];
    const float* lnfg = (const float*)d_in[21];
    const float* lnfb = (const float*)d_in[22];
    float* out = (float*)d_out;

    cudaFuncSetAttribute(twbias_kernel, cudaFuncAttributeMaxDynamicSharedMemorySize, TW_SMEM);
    cudaFuncSetAttribute(tail_kernel, cudaFuncAttributeMaxDynamicSharedMemorySize, TAIL_SMEM);

    bimg_kernel<<<128, 256>>>(Wt);
    twbias_kernel<<<2048, 256, TW_SMEM>>>(tmk, bt, Wtp, btp);
    tail_kernel<<<NCTA, 512, TAIL_SMEM>>>(logs, seqs, Wq, bq, Wk, bk, Wv, bv,
                                          ln1g, ln1b, ln2g, ln2b, W1, b1, W2, b2,
                                          lnfg, lnfb, out);
}

// round 17
// speedup vs baseline: 1.4862x; 1.4862x over previous
#include <cuda_runtime.h>
#include <cuda_bf16.h>
#include <cuda_fp8.h>
#include <cstdint>

#define LL 512
#define DD 128
#define NCTA 128

// ---------------- scratch globals ----------------
__device__ float g_keep[LL];
__device__ float g_seq[LL * DD];
__device__ float g_Q[LL * DD];
__device__ float g_qp[LL * DD];
__device__ float g_kp[LL * DD];
__device__ float g_vp[LL * DD];
__device__ float g_twlog[2 * LL * LL];
__device__ __align__(16) uint8_t g_Bimg8[2 * 128 * 128];  // e4m3(64*Wt[s][k][n]) as [s][n][k]

__device__ unsigned g_bar_count;
__device__ volatile unsigned g_bar_gen;

__device__ __forceinline__ void grid_barrier() {
    __syncthreads();
    if (threadIdx.x == 0) {
        __threadfence();
        unsigned gen = g_bar_gen;
        if (atomicAdd(&g_bar_count, 1u) == NCTA - 1) {
            atomicExch(&g_bar_count, 0u);
            __threadfence();
            g_bar_gen = gen + 1u;
        } else {
            while (g_bar_gen == gen) __nanosleep(32);
        }
        __threadfence();
    }
    __syncthreads();
}

// fp8 e4m3 MMA: D[16x8] += A[16x32] * B[32x8], fp32 accum
__device__ __forceinline__ void mma_fp8(float* c, const uint32_t* a, uint32_t b0, uint32_t b1) {
    asm volatile(
        "mma.sync.aligned.m16n8k32.row.col.f32.e4m3.e4m3.f32 "
        "{%0,%1,%2,%3}, {%4,%5,%6,%7}, {%8,%9}, {%0,%1,%2,%3};"
        : "+f"(c[0]), "+f"(c[1]), "+f"(c[2]), "+f"(c[3])
        : "r"(a[0]), "r"(a[1]), "r"(a[2]), "r"(a[3]), "r"(b0), "r"(b1));
}

// pack 4 floats -> 4 e4m3 bytes (byte i = element i)
__device__ __forceinline__ uint32_t pack_e4m3x4(float4 a) {
    uint16_t lo, hi;
    asm("cvt.rn.satfinite.e4m3x2.f32 %0, %1, %2;" : "=h"(lo) : "f"(a.y), "f"(a.x));
    asm("cvt.rn.satfinite.e4m3x2.f32 %0, %1, %2;" : "=h"(hi) : "f"(a.w), "f"(a.z));
    return (uint32_t)lo | ((uint32_t)hi << 16);
}

// ---------------- B images: g_Bimg8[s][n][k] = e4m3(64 * Wt[s][k][n]) --------
__global__ void bimg_kernel(const float* __restrict__ Wt) {
    int id = blockIdx.x * 256 + threadIdx.x;  // 32768
    int s = id >> 14, e = id & 16383;
    int n = e >> 7, k = e & 127;
    float v = Wt[s * 16384 + k * 128 + n] * 64.0f;
    g_Bimg8[id] = (uint8_t)__nv_cvt_float_to_fp8(v, __NV_SATFINITE, __NV_E4M3);
}

// ---------------- time-bias kernel: fp8 MMA, 64 rows/CTA, 3 CTAs/SM ----------
// smem: A fp8 64x144, B 2x128x144, scalars
#define TW_SA   0
#define TW_SB   9216
#define TW_SSC  (TW_SB + 36864)          // 46080
#define TW_SMEM (TW_SSC + 2064)          // 48144

__global__ void __launch_bounds__(256, 3)
twbias_kernel(const float* __restrict__ T, const float* __restrict__ bt,
              const float* __restrict__ Wtp, const float* __restrict__ btp) {
    extern __shared__ char smem[];
    int tid = threadIdx.x;
    float* sc = (float*)(smem + TW_SSC);

    {   // stage B images: 256 rows x 128B -> padded 144B rows
        const uint4* src = (const uint4*)g_Bimg8;   // 2048 uint4
        for (int i = tid; i < 2048; i += 256) {
            int r = i >> 3, w8 = i & 7;             // row r in [0,256), 16B chunk w8
            int s = r >> 7, n = r & 127;
            *(uint4*)(smem + TW_SB + s * 18432 + n * 144 + w8 * 16) = src[i];
        }
    }
    if (tid < 128) {
        sc[tid]       = bt[tid];
        sc[128 + tid] = bt[128 + tid];
        sc[256 + tid] = Wtp[tid];
        sc[384 + tid] = Wtp[128 + tid];
    }
    if (tid == 0) { sc[512] = btp[0]; sc[513] = btp[1]; }

    {   // A tile: 64 rows x 128 fp32 -> e4m3, stride 144B (flat high-MLP loads)
        const float4* Tb = (const float4*)(T + (size_t)blockIdx.x * 64 * 128);
#pragma unroll
        for (int i = 0; i < 8; i++) {
            int c = tid + 256 * i;                  // 2048 float4 chunks
            int r = c >> 5, kc = (c & 31) << 2;
            *(uint32_t*)(smem + TW_SA + r * 144 + kc) = pack_e4m3x4(Tb[c]);
        }
    }
    __syncthreads();

    int lane = tid & 31, w = tid >> 5;
    int s = w >> 2, mrow0 = (w & 3) * 16;           // warp owns one 16-row mtile, one set
    int gid = lane >> 2, tig = lane & 3;

    // A fragments: 4 ktiles x 4 regs (PTX m16n8k32 f8 layout)
    uint32_t a8[4][4];
#pragma unroll
    for (int kt = 0; kt < 4; kt++) {
        const char* rp0 = smem + TW_SA + (mrow0 + gid) * 144;
        const char* rp1 = rp0 + 8 * 144;
        int k0 = kt * 32 + tig * 4;
        a8[kt][0] = *(const uint32_t*)(rp0 + k0);
        a8[kt][1] = *(const uint32_t*)(rp1 + k0);
        a8[kt][2] = *(const uint32_t*)(rp0 + k0 + 16);
        a8[kt][3] = *(const uint32_t*)(rp1 + k0 + 16);
    }

    const char* b_base = smem + TW_SB + s * 18432;
    const float IS = 0.015625f;   // 1/64: undo the Wt*64 quantization scale

    float accR[2] = {0.f, 0.f};
#pragma unroll
    for (int nt = 0; nt < 16; nt++) {
        float c[4] = {0.f, 0.f, 0.f, 0.f};
        const char* brow = b_base + (nt * 8 + gid) * 144;
#pragma unroll
        for (int kt = 0; kt < 4; kt++) {
            int k0 = kt * 32 + tig * 4;
            uint32_t b0 = *(const uint32_t*)(brow + k0);
            uint32_t b1 = *(const uint32_t*)(brow + k0 + 16);
            mma_fp8(c, a8[kt], b0, b1);
        }
        int n0 = nt * 8 + 2 * tig;
        float bt0 = sc[s * 128 + n0],       bt1 = sc[s * 128 + n0 + 1];
        float wp0 = sc[256 + s * 128 + n0], wp1 = sc[256 + s * 128 + n0 + 1];
        accR[0] += fmaxf(fmaf(c[0], IS, bt0), 0.f) * wp0 + fmaxf(fmaf(c[1], IS, bt1), 0.f) * wp1;
        accR[1] += fmaxf(fmaf(c[2], IS, bt0), 0.f) * wp0 + fmaxf(fmaf(c[3], IS, bt1), 0.f) * wp1;
    }
    // reduce over quad
#pragma unroll
    for (int o = 1; o <= 2; o <<= 1) {
        accR[0] += __shfl_xor_sync(0xffffffffu, accR[0], o);
        accR[1] += __shfl_xor_sync(0xffffffffu, accR[1], o);
    }
    if ((lane & 3) == 0) {
        int g = lane >> 2;
        float bp = sc[512 + s];
#pragma unroll
        for (int hh = 0; hh < 2; hh++) {
            int row = mrow0 + hh * 8 + g;
            size_t p = (size_t)blockIdx.x * 64 + (size_t)row;
            float tp = accR[hh] + bp;
            float lg = (tp >= 0.f) ? -log1pf(expf(-tp)) : tp - log1pf(expf(tp));
            g_twlog[(size_t)s * (LL * LL) + p] = lg;
        }
    }
}

// ---- warp-cooperative row LN stats: warps 0-3 reduce rows 0-3 of rowbuf[4][128]
__device__ __forceinline__ void row_stats(const float* rowbuf, float* stats,
                                          int w, int lane) {
    if (w < 4) {
        float s = 0.f, s2 = 0.f;
#pragma unroll
        for (int j = 0; j < 4; j++) {
            float v = rowbuf[w * 128 + lane + 32 * j];
            s += v; s2 += v * v;
        }
#pragma unroll
        for (int o = 16; o; o >>= 1) {
            s  += __shfl_xor_sync(0xffffffffu, s, o);
            s2 += __shfl_xor_sync(0xffffffffu, s2, o);
        }
        if (lane == 0) {
            float m = s * (1.0f / DD);
            float var = s2 * (1.0f / DD) - m * m;
            stats[w * 2]     = m;
            stats[w * 2 + 1] = rsqrtf(var + 1e-8f);
        }
    }
    __syncthreads();
}

// ---------------- persistent fused tail (R12/R14 form): 128 CTAs x 512 thr --
#define TAIL_SMEM (2 * 512 * 33 * 4)    // 135168 B

__global__ void __launch_bounds__(512)
tail_kernel(const int* __restrict__ logs, const float* __restrict__ seqs,
            const float* __restrict__ Wq, const float* __restrict__ bq,
            const float* __restrict__ Wk, const float* __restrict__ bk,
            const float* __restrict__ Wv, const float* __restrict__ bv,
            const float* __restrict__ ln1g, const float* __restrict__ ln1b,
            const float* __restrict__ ln2g, const float* __restrict__ ln2b,
            const float* __restrict__ W1, const float* __restrict__ b1,
            const float* __restrict__ W2, const float* __restrict__ b2,
            const float* __restrict__ lnfg, const float* __restrict__ lnfb,
            float* __restrict__ out) {
    extern __shared__ float fsm[];
    float* rows_raw = fsm;
    float* rows_ln  = fsm + 512;
    float* hbuf     = fsm + 1024;
    float* stats    = fsm + 1536;
    float* Ws       = fsm + 2048;

    int cta = blockIdx.x, tid = threadIdx.x;
    int lane = tid & 31, w = tid >> 5;
    int trow = tid >> 7, tcol = tid & 127;
    int grow = cta * 4 + trow;
    const float NEGV = -4294967295.0f;
    const float SCALE = 0.17677669529663689f;  // 1/sqrt(32)

    for (int i = 0; i < 2; i++) {
        const int wo = i * 16384, bo = i * 128;

        // ======== phase A: (prep +) ln1 + Q/K/V for own 4 rows ========
        if (i == 0) {
            float kmask = (logs[grow] == 0) ? 0.f : 1.f;
            rows_raw[tid] = seqs[grow * 128 + tcol] * kmask;
            if (tcol == 0) g_keep[grow] = kmask;
        } else {
            rows_raw[tid] = g_seq[grow * 128 + tcol];
        }
        __syncthreads();
        row_stats(rows_raw, stats, w, lane);
        {
            float m = stats[trow * 2], rinv = stats[trow * 2 + 1];
            float lv = (rows_raw[tid] - m) * rinv * ln1g[bo + tcol] + ln1b[bo + tcol];
            rows_ln[tid] = lv;
            g_Q[grow * 128 + tcol] = lv;
        }
        __syncthreads();
#pragma unroll 1
        for (int z = 0; z < 3; z++) {
            const float* W    = (z == 0) ? Wq + wo : (z == 1) ? Wk + wo : Wv + wo;
            const float* bias = (z == 0) ? bq + bo : (z == 1) ? bk + bo : bv + bo;
            float* C          = (z == 0) ? g_qp : (z == 1) ? g_kp : g_vp;
            const float4* Wsrc = (const float4*)W;
            float4* Wdst = (float4*)Ws;
#pragma unroll
            for (int j = 0; j < 8; j++) Wdst[tid + 512 * j] = Wsrc[tid + 512 * j];
            __syncthreads();
            const float* src = (z == 0) ? rows_ln : rows_raw;
            float a0 = 0.f, a1 = 0.f, a2 = 0.f, a3 = 0.f;
#pragma unroll
            for (int k = 0; k < 128; k += 4) {
                a0 += src[trow * 128 + k]     * Ws[(k) * 128 + tcol];
                a1 += src[trow * 128 + k + 1] * Ws[(k + 1) * 128 + tcol];
                a2 += src[trow * 128 + k + 2] * Ws[(k + 2) * 128 + tcol];
                a3 += src[trow * 128 + k + 3] * Ws[(k + 3) * 128 + tcol];
            }
            C[grow * 128 + tcol] = (a0 + a1) + (a2 + a3) + bias[tcol];
            __syncthreads();
        }
        grid_barrier();

        // ======== phase B: attention, CTA=(h, q-chunk of 16), warp-per-q ====
        {
            float* ks = fsm;
            float* vs = fsm + 512 * 33;
            int h = cta >> 5, q0 = (cta & 31) * 16;
            for (int t = tid; t < 512 * 32; t += 512) {
                int kk = t >> 5, d = t & 31;
                ks[kk * 33 + d] = g_kp[kk * 128 + h * 32 + d];
                vs[kk * 33 + d] = g_vp[kk * 128 + h * 32 + d];
            }
            __syncthreads();
            float* wout = out + 65536 + (size_t)i * 1048576;
            int q = q0 + w;
            float qreg[32];
            const float4* q4 = (const float4*)(g_qp + q * 128 + h * 32);
#pragma unroll
            for (int j = 0; j < 8; j++) {
                float4 t4 = q4[j];
                qreg[j * 4]     = t4.x; qreg[j * 4 + 1] = t4.y;
                qreg[j * 4 + 2] = t4.z; qreg[j * 4 + 3] = t4.w;
            }
            bool padq = (g_keep[q] == 0.0f);
            const float* tw = g_twlog + (size_t)i * (LL * LL) + (size_t)q * 512;
            float sv[16];
            float mx = -3.4e38f;
#pragma unroll
            for (int blk = 0; blk < 16; blk++) {
                int kk = blk * 32 + lane;
                float d0 = 0.f, d1 = 0.f;
#pragma unroll
                for (int d = 0; d < 32; d += 2) {
                    d0 += qreg[d]     * ks[kk * 33 + d];
                    d1 += qreg[d + 1] * ks[kk * 33 + d + 1];
                }
                float sva = (padq || kk > q) ? NEGV : ((d0 + d1) + tw[kk]) * SCALE;
                sv[blk] = sva;
                mx = fmaxf(mx, sva);
            }
#pragma unroll
            for (int o = 16; o; o >>= 1) mx = fmaxf(mx, __shfl_xor_sync(0xffffffffu, mx, o));
            float sum = 0.f;
#pragma unroll
            for (int blk = 0; blk < 16; blk++) {
                float e = expf(sv[blk] - mx);
                sv[blk] = e;
                sum += e;
            }
#pragma unroll
            for (int o = 16; o; o >>= 1) sum += __shfl_xor_sync(0xffffffffu, sum, o);
            float inv = 1.0f / sum;
#pragma unroll
            for (int blk = 0; blk < 16; blk++) {
                float wv = sv[blk] * inv;
                sv[blk] = wv;
                wout[(size_t)h * 262144 + (size_t)q * 512 + blk * 32 + lane] = wv;
            }
            float ac0 = 0.f, ac1 = 0.f, ac2 = 0.f, ac3 = 0.f;
#pragma unroll
            for (int blk = 0; blk < 16; blk++) {
#pragma unroll
                for (int src = 0; src < 32; src += 4) {
                    ac0 += __shfl_sync(0xffffffffu, sv[blk], src)     * vs[(blk * 32 + src) * 33 + lane];
                    ac1 += __shfl_sync(0xffffffffu, sv[blk], src + 1) * vs[(blk * 32 + src + 1) * 33 + lane];
                    ac2 += __shfl_sync(0xffffffffu, sv[blk], src + 2) * vs[(blk * 32 + src + 2) * 33 + lane];
                    ac3 += __shfl_sync(0xffffffffu, sv[blk], src + 3) * vs[(blk * 32 + src + 3) * 33 + lane];
                }
            }
            float acc = (ac0 + ac1) + (ac2 + ac3);
            g_seq[q * 128 + h * 32 + lane] = g_Q[q * 128 + h * 32 + lane] + acc;
            __syncthreads();
        }
        grid_barrier();

        // ======== phase C: ln2 + FFN1 (own rows, h kept in smem) ========
        rows_raw[tid] = g_seq[grow * 128 + tcol];
        __syncthreads();
        row_stats(rows_raw, stats, w, lane);
        {
            float m = stats[trow * 2], rinv = stats[trow * 2 + 1];
            rows_ln[tid] = (rows_raw[tid] - m) * rinv * ln2g[bo + tcol] + ln2b[bo + tcol];
        }
        __syncthreads();
        {
            const float4* Wsrc = (const float4*)(W1 + wo);
            float4* Wdst = (float4*)Ws;
#pragma unroll
            for (int j = 0; j < 8; j++) Wdst[tid + 512 * j] = Wsrc[tid + 512 * j];
            __syncthreads();
            float a0 = 0.f, a1 = 0.f, a2 = 0.f, a3 = 0.f;
#pragma unroll
            for (int k = 0; k < 128; k += 4) {
                a0 += rows_ln[trow * 128 + k]     * Ws[(k) * 128 + tcol];
                a1 += rows_ln[trow * 128 + k + 1] * Ws[(k + 1) * 128 + tcol];
                a2 += rows_ln[trow * 128 + k + 2] * Ws[(k + 2) * 128 + tcol];
                a3 += rows_ln[trow * 128 + k + 3] * Ws[(k + 3) * 128 + tcol];
            }
            hbuf[tid] = fmaxf((a0 + a1) + (a2 + a3) + b1[bo + tcol], 0.f);
            __syncthreads();
        }
        // ======== phase D: FFN2 (local) ========
        {
            const float4* Wsrc = (const float4*)(W2 + wo);
            float4* Wdst = (float4*)Ws;
#pragma unroll
            for (int j = 0; j < 8; j++) Wdst[tid + 512 * j] = Wsrc[tid + 512 * j];
            __syncthreads();
            float a0 = 0.f, a1 = 0.f, a2 = 0.f, a3 = 0.f;
#pragma unroll
            for (int k = 0; k < 128; k += 4) {
                a0 += hbuf[trow * 128 + k]     * Ws[(k) * 128 + tcol];
                a1 += hbuf[trow * 128 + k + 1] * Ws[(k + 1) * 128 + tcol];
                a2 += hbuf[trow * 128 + k + 2] * Ws[(k + 2) * 128 + tcol];
                a3 += hbuf[trow * 128 + k + 3] * Ws[(k + 3) * 128 + tcol];
            }
            float y = (a0 + a1) + (a2 + a3) + b2[bo + tcol];
            g_seq[grow * 128 + tcol] = (rows_ln[tid] + y) * g_keep[grow];
            __syncthreads();
        }
        // no grid barrier: next phase A / lnf read only own rows
    }

    // ======== final LayerNorm (own rows) ========
    rows_raw[tid] = g_seq[grow * 128 + tcol];
    __syncthreads();
    row_stats(rows_raw, stats, w, lane);
    {
        float m = stats[trow * 2], rinv = stats[trow * 2 + 1];
        out[grow * 128 + tcol] =
            (rows_raw[tid] - m) * rinv * lnfg[tcol] + lnfb[tcol];
    }
}

// ---------------- launch ----------------
extern "C" void kernel_launch(void* const* d_in, const int* in_sizes, int n_in,
                              void* d_out, int out_size) {
    const int*   logs = (const int*)d_in[0];
    const float* seqs = (const float*)d_in[1];
    const float* tmk  = (const float*)d_in[2];
    const float* Wq   = (const float*)d_in[3];
    const float* bq   = (const float*)d_in[4];
    const float* Wk   = (const float*)d_in[5];
    const float* bk   = (const float*)d_in[6];
    const float* Wv   = (const float*)d_in[7];
    const float* bv   = (const float*)d_in[8];
    const float* Wt   = (const float*)d_in[9];
    const float* bt   = (const float*)d_in[10];
    const float* Wtp  = (const float*)d_in[11];
    const float* btp  = (const float*)d_in[12];
    const float* ln1g = (const float*)d_in[13];
    const float* ln1b = (const float*)d_in[14];
    const float* ln2g = (const float*)d_in[15];
    const float* ln2b = (const float*)d_in[16];
    const float* W1   = (const float*)d_in[17];
    const float* b1   = (const float*)d_in[18];
    const float* W2   = (const float*)d_in[19];
    const float* b2   = (const float*)d_in[20];
    const float* lnfg = (const float*)d_in[21];
    const float* lnfb = (const float*)d_in[22];
    float* out = (float*)d_out;

    cudaFuncSetAttribute(twbias_kernel, cudaFuncAttributeMaxDynamicSharedMemorySize, TW_SMEM);
    cudaFuncSetAttribute(tail_kernel, cudaFuncAttributeMaxDynamicSharedMemorySize, TAIL_SMEM);

    bimg_kernel<<<128, 256>>>(Wt);
    twbias_kernel<<<4096, 256, TW_SMEM>>>(tmk, bt, Wtp, btp);
    tail_kernel<<<NCTA, 512, TAIL_SMEM>>>(logs, seqs, Wq, bq, Wk, bk, Wv, bv,
                                          ln1g, ln1b, ln2g, ln2b, W1, b1, W2, b2,
                                          lnfg, lnfb, out);
}